// round 11
// baseline (speedup 1.0000x reference)
#include <cuda_runtime.h>
#include <cuda_fp16.h>
#include <cstdint>
#include <cstddef>

#define FULLMASK 0xffffffffu

constexpr int Bx    = 2;
constexpr int Npt   = 20000;
constexpr int Cdim  = 256;
constexpr int Kn    = 16;
constexpr int Hdim  = 128;
constexpr int Mrows = Bx * Npt;   // 40000

// ---------------- scratch (device globals: allocation-free) ----------------
__device__ __half g_Q[(size_t)3 * Mrows * Cdim];
__device__ __half g_K[(size_t)3 * Mrows * Cdim];
__device__ __half g_V[(size_t)3 * Mrows * Cdim];
__device__ __half g_H[(size_t)Mrows * Hdim];
__device__ __half g_X3h[(size_t)Mrows * Cdim];

// ---------------- fp16 GEMM (balanced persistent + B-resident) ------------
struct GemmJob {
    const void*  A;        // float* (a_half=0) or __half* (a_half=1)
    const float* W;
    const float* bias;
    void*        C;
    int          ncols;
    int          relu;
    int          a_half;
};
struct GemmJobs { GemmJob j[10]; };

constexpr int BM = 128;               // M tile
constexpr int BK = 32;                // k chunk
constexpr int KTILES = Cdim / BK;     // 8
constexpr int LDSA = 40;              // A smem stride (halfs): LDSM conflict-free
constexpr int LDSB = 264;             // B smem stride (halfs): LDSM conflict-free
constexpr int MTILES = (Mrows + BM - 1) / BM;   // 313
constexpr int NJOBCOL = 19;           // jobs 0..8 x 2 col-halves + job 9 x 1
constexpr int TOTAL_ITEMS = NJOBCOL * MTILES;   // 5947
constexpr int GRID_CTAS = 148;

// dynamic smem carve
constexpr int SMB_OFF = 0;
constexpr int SMB_BYTES = 128 * LDSB * 2;          // 67584
constexpr int SMA_OFF = SMB_BYTES;
constexpr int SMA_BYTES = 2 * BM * LDSA * 2;       // 20480 (2 buffers)
constexpr int SM_TOT = SMA_OFF + SMA_BYTES;        // 88064

__device__ __forceinline__ uint32_t smem_u32(const void* p) {
    uint32_t a;
    asm("{ .reg .u64 t; cvta.to.shared.u64 t, %1; cvt.u32.u64 %0, t; }" : "=r"(a) : "l"(p));
    return a;
}
__device__ __forceinline__ uint2 f4toh4(float4 v) {
    union { __half2 h; unsigned u; } a, b;
    a.h = __floats2half2_rn(v.x, v.y);
    b.h = __floats2half2_rn(v.z, v.w);
    return make_uint2(a.u, b.u);
}
__device__ __forceinline__ void ldsm4(unsigned r[4], uint32_t addr) {
    asm volatile("ldmatrix.sync.aligned.m8n8.x4.shared.b16 {%0,%1,%2,%3}, [%4];"
        : "=r"(r[0]), "=r"(r[1]), "=r"(r[2]), "=r"(r[3]) : "r"(addr));
}
__device__ __forceinline__ void mma16(float c[4], const unsigned a[4], const unsigned b[2]) {
    asm volatile(
        "mma.sync.aligned.m16n8k16.row.col.f32.f16.f16.f32 "
        "{%0,%1,%2,%3}, {%4,%5,%6,%7}, {%8,%9}, {%0,%1,%2,%3};\n"
        : "+f"(c[0]), "+f"(c[1]), "+f"(c[2]), "+f"(c[3])
        : "r"(a[0]), "r"(a[1]), "r"(a[2]), "r"(a[3]), "r"(b[0]), "r"(b[1]));
}

__global__ __launch_bounds__(256, 1) void gemm_fp16_kernel(GemmJobs jobs) {
    const int per = (TOTAL_ITEMS + (int)gridDim.x - 1) / (int)gridDim.x;  // 41
    const int it0 = (int)blockIdx.x * per;
    const int it1 = min(it0 + per, TOTAL_ITEMS);
    if (it0 >= TOTAL_ITEMS) return;

    extern __shared__ char sm[];
    __half* Bres = (__half*)(sm + SMB_OFF);
    __half* Asm  = (__half*)(sm + SMA_OFF);   // [2][BM][LDSA]

    const int tid  = threadIdx.x;
    const int lane = tid & 31;
    const int warp = tid >> 5;       // 0..7
    const int g    = lane >> 2;      // 0..7
    const int t4   = lane & 3;       // 0..3
    const int m0w  = (warp & 1) * 64;
    const int n0w  = (warp >> 1) * 32;

    const int lr = tid >> 3;         // 0..31 (fp32 staging row)
    const int lc = (tid & 7) * 4;    // 0,4,..,28
    const int hr0 = tid >> 2;        // fp16 staging row (0..63)
    const int hc  = (tid & 3) * 8;   // half-offset 0,8,16,24

    const int rowA = lane & 15;
    const int kA8  = (lane >> 4) * 8;
    const int rowB = (lane & 7) + ((lane >> 4) << 3);
    const int kB8  = ((lane >> 3) & 1) << 3;

    const uint32_t sA = smem_u32(Asm);
    const uint32_t sB = smem_u32(Bres);

    int curJC = -1;
    GemmJob jb;
    int yoff = 0;

    for (int it = it0; it < it1; ++it) {
        const int jc = it / MTILES;
        const int mt = it - jc * MTILES;

        if (jc != curJC) {
            curJC = jc;
            const int job = (jc < 18) ? (jc >> 1) : 9;
            yoff = (jc < 18) ? ((jc & 1) * 128) : 0;
            jb = jobs.j[job];
            __syncthreads();   // prior tile's B reads complete
            for (int idx = tid; idx < 128 * 64; idx += 256) {
                const int r  = idx >> 6;
                const int c4 = (idx & 63) * 4;
                const float4 v = *(const float4*)(jb.W + (size_t)(yoff + r) * Cdim + c4);
                *(uint2*)&Bres[r * LDSB + c4] = f4toh4(v);
            }
            __syncthreads();
        }

        const int rowBase = mt * BM;
        const int ldc = jb.ncols;
        const int aHalf = jb.a_half;

        float acc[4][4][4];
#pragma unroll
        for (int mtile = 0; mtile < 4; ++mtile)
#pragma unroll
            for (int nt = 0; nt < 4; ++nt)
#pragma unroll
                for (int e = 0; e < 4; ++e) acc[mtile][nt][e] = 0.f;

        // ---- prologue: stage chunk 0 into buf 0 ----
        if (aHalf) {
            const __half* Ah = (const __half*)jb.A;
#pragma unroll
            for (int i = 0; i < 2; ++i) {
                const int r = hr0 + i * 64;
                const int ra = min(rowBase + r, Mrows - 1);
                *(uint4*)&Asm[(0 * BM + r) * LDSA + hc] =
                    *(const uint4*)(Ah + (size_t)ra * Cdim + hc);
            }
        } else {
            const float* Af = (const float*)jb.A;
#pragma unroll
            for (int i = 0; i < 4; ++i) {
                const int ra = min(rowBase + lr + i * 32, Mrows - 1);
                const float4 v = *(const float4*)(Af + (size_t)ra * Cdim + lc);
                *(uint2*)&Asm[(0 * BM + lr + i * 32) * LDSA + lc] = f4toh4(v);
            }
        }
        __syncthreads();

        for (int kt = 0; kt < KTILES; ++kt) {
            const int buf = kt & 1;
            float4 aRegF[4];
            uint4  aRegH[2];
            if (kt + 1 < KTILES) {
                const int ko = (kt + 1) * BK;
                if (aHalf) {
                    const __half* Ah = (const __half*)jb.A;
#pragma unroll
                    for (int i = 0; i < 2; ++i) {
                        const int r = hr0 + i * 64;
                        const int ra = min(rowBase + r, Mrows - 1);
                        aRegH[i] = *(const uint4*)(Ah + (size_t)ra * Cdim + ko + hc);
                    }
                } else {
                    const float* Af = (const float*)jb.A;
#pragma unroll
                    for (int i = 0; i < 4; ++i) {
                        const int ra = min(rowBase + lr + i * 32, Mrows - 1);
                        aRegF[i] = *(const float4*)(Af + (size_t)ra * Cdim + ko + lc);
                    }
                }
            }
#pragma unroll
            for (int ks = 0; ks < 2; ++ks) {
                const int kloc = ks * 16;
                const int kglb = kt * BK + kloc;
                unsigned afr[4][4];
#pragma unroll
                for (int mtile = 0; mtile < 4; ++mtile) {
                    const uint32_t addr = sA +
                        (uint32_t)(((buf * BM) + m0w + mtile * 16 + rowA) * LDSA + kloc + kA8) * 2;
                    ldsm4(afr[mtile], addr);
                }
                unsigned bfr[4][2];
#pragma unroll
                for (int ntp = 0; ntp < 2; ++ntp) {
                    unsigned q[4];
                    const uint32_t addr = sB +
                        (uint32_t)((n0w + ntp * 16 + rowB) * LDSB + kglb + kB8) * 2;
                    ldsm4(q, addr);
                    bfr[2 * ntp][0]     = q[0];
                    bfr[2 * ntp][1]     = q[1];
                    bfr[2 * ntp + 1][0] = q[2];
                    bfr[2 * ntp + 1][1] = q[3];
                }
#pragma unroll
                for (int mtile = 0; mtile < 4; ++mtile)
#pragma unroll
                    for (int nt = 0; nt < 4; ++nt)
                        mma16(acc[mtile][nt], afr[mtile], bfr[nt]);
            }
            if (kt + 1 < KTILES) {
                const int nb = buf ^ 1;
                if (aHalf) {
#pragma unroll
                    for (int i = 0; i < 2; ++i) {
                        const int r = hr0 + i * 64;
                        *(uint4*)&Asm[(nb * BM + r) * LDSA + hc] = aRegH[i];
                    }
                } else {
#pragma unroll
                    for (int i = 0; i < 4; ++i)
                        *(uint2*)&Asm[(nb * BM + lr + i * 32) * LDSA + lc] = f4toh4(aRegF[i]);
                }
                __syncthreads();
            }
        }

        // epilogue: bias (+relu), fp16 store, row-guarded
#pragma unroll
        for (int mtile = 0; mtile < 4; ++mtile) {
#pragma unroll
            for (int nt = 0; nt < 4; ++nt) {
                const int row = rowBase + m0w + mtile * 16 + g;
                const int col = yoff + n0w + nt * 8 + t4 * 2;
                const float b0 = jb.bias[col];
                const float b1 = jb.bias[col + 1];
                float v0 = acc[mtile][nt][0] + b0;
                float v1 = acc[mtile][nt][1] + b1;
                float v2 = acc[mtile][nt][2] + b0;
                float v3 = acc[mtile][nt][3] + b1;
                if (jb.relu) {
                    v0 = fmaxf(v0, 0.f); v1 = fmaxf(v1, 0.f);
                    v2 = fmaxf(v2, 0.f); v3 = fmaxf(v3, 0.f);
                }
                __half* C = (__half*)jb.C;
                if (row < Mrows)
                    *(__half2*)(C + (size_t)row * ldc + col) = __floats2half2_rn(v0, v1);
                if (row + 8 < Mrows)
                    *(__half2*)(C + (size_t)(row + 8) * ldc + col) = __floats2half2_rn(v2, v3);
            }
        }
        __syncthreads();   // A-buffer reads done before next tile's staging
    }
}

// ---------------- x3 -> fp16 convert --------------------------------------
__global__ __launch_bounds__(256) void cvt_x3_kernel(const float* __restrict__ x3) {
    const int idx = (int)(blockIdx.x * blockDim.x + threadIdx.x);   // 4 floats each
    const float4 v = ((const float4*)x3)[idx];
    *(uint2*)&g_X3h[(size_t)idx * 4] = f4toh4(v);
}

// ---------------- warp sum ------------------------------------------------
__device__ __forceinline__ float wsum(float p) {
#pragma unroll
    for (int off = 16; off; off >>= 1) p += __shfl_xor_sync(FULLMASK, p, off);
    return p;
}

// ------- fused: gate + KNN attention x3 + LN x3 + alpha + final LN --------
__device__ __forceinline__ void h8tof(uint4 v, float f[8]) {
    const __half2* h = (const __half2*)&v;
    const float2 a = __half22float2(h[0]);
    const float2 b = __half22float2(h[1]);
    const float2 c = __half22float2(h[2]);
    const float2 d = __half22float2(h[3]);
    f[0] = a.x; f[1] = a.y; f[2] = b.x; f[3] = b.y;
    f[4] = c.x; f[5] = c.y; f[6] = d.x; f[7] = d.y;
}

// ---- packed f32x2 helpers (sm_100+ PTX, no 'a' suffix required) ----
typedef unsigned long long u64t;
__device__ __forceinline__ u64t pack2(float lo, float hi) {
    u64t d;
    asm("mov.b64 %0, {%1, %2};" : "=l"(d) : "f"(lo), "f"(hi));
    return d;
}
__device__ __forceinline__ void unpack2(u64t d, float& lo, float& hi) {
    asm("mov.b64 {%0, %1}, %2;" : "=f"(lo), "=f"(hi) : "l"(d));
}
__device__ __forceinline__ u64t fma2p(u64t a, u64t b, u64t c) {
    u64t d;
    asm("fma.rn.f32x2 %0, %1, %2, %3;" : "=l"(d) : "l"(a), "l"(b), "l"(c));
    return d;
}
__device__ __forceinline__ u64t add2p(u64t a, u64t b) {
    u64t d;
    asm("add.rn.f32x2 %0, %1, %2;" : "=l"(d) : "l"(a), "l"(b));
    return d;
}
__device__ __forceinline__ void h8top4(uint4 v, u64t p[4]) {
    const __half2* h = (const __half2*)&v;
#pragma unroll
    for (int i = 0; i < 4; ++i) {
        const float2 f = __half22float2(h[i]);
        p[i] = pack2(f.x, f.y);
    }
}

__global__ __launch_bounds__(256, 3) void attn_kernel(
    const int* __restrict__ knn,
    const float* __restrict__ Wg2, const float* __restrict__ bg2,
    const float* __restrict__ ln_g, const float* __restrict__ ln_b,
    const float* __restrict__ fn_g, const float* __restrict__ fn_b,
    float* __restrict__ out) {
    const int w    = (int)((blockIdx.x * blockDim.x + threadIdx.x) >> 5);
    const int lane = threadIdx.x & 31;
    if (w >= Mrows) return;
    const int b = w / Npt;
    const int n = w - b * Npt;

    const int idx_l = (lane < Kn) ? knn[n * Kn + lane] : 0;

    // ---- inline gate: alpha = softmax(h @ Wg2^T + bg2) ----
    float alph[3];
    {
        const uint2 hv = *(const uint2*)(g_H + (size_t)w * Hdim + lane * 4);
        const __half2* hh = (const __half2*)&hv;
        const float2 h01 = __half22float2(hh[0]);
        const float2 h23 = __half22float2(hh[1]);
        float d[3];
#pragma unroll
        for (int i = 0; i < 3; ++i) {
            const float4 ww = ((const float4*)(Wg2 + i * Hdim))[lane];
            float p = h01.x * ww.x + h01.y * ww.y + h23.x * ww.z + h23.y * ww.w;
            d[i] = wsum(p) + bg2[i];
        }
        const float m  = fmaxf(d[0], fmaxf(d[1], d[2]));
        const float e0 = __expf(d[0] - m);
        const float e1 = __expf(d[1] - m);
        const float e2 = __expf(d[2] - m);
        const float inv = 1.f / (e0 + e1 + e2);
        alph[0] = e0 * inv; alph[1] = e1 * inv; alph[2] = e2 * inv;
    }

    const bool h4 = (lane & 16) != 0;
    const bool h3 = (lane & 8)  != 0;
    const bool h2 = (lane & 4)  != 0;
    const bool h1 = (lane & 2)  != 0;

    float acc[8] = {0.f, 0.f, 0.f, 0.f, 0.f, 0.f, 0.f, 0.f};

    for (int i = 0; i < 3; ++i) {
        const uint4 qraw = *(const uint4*)(g_Q + ((size_t)i * Mrows + w) * Cdim + lane * 8);
        const __half2* qh = (const __half2*)&qraw;
        u64t q2[4];
        h8top4(qraw, q2);
        const __half* Kbase = g_K + ((size_t)i * Mrows + (size_t)b * Npt) * Cdim;
        const __half* Vbase = g_V + ((size_t)i * Mrows + (size_t)b * Npt) * Cdim;

        // per-lane partial dots for all 16 neighbors (fp16 accumulate)
        float s[Kn];
#pragma unroll
        for (int k = 0; k < Kn; ++k) {
            const int j = __shfl_sync(FULLMASK, idx_l, k);
            const uint4 kvr = *(const uint4*)(Kbase + (size_t)j * Cdim + lane * 8);
            const __half2* kh = (const __half2*)&kvr;
            __half2 a0 = __hmul2(qh[0], kh[0]);
            __half2 a1 = __hmul2(qh[1], kh[1]);
            a0 = __hfma2(qh[2], kh[2], a0);
            a1 = __hfma2(qh[3], kh[3], a1);
            const float2 f = __half22float2(__hadd2(a0, a1));
            s[k] = f.x + f.y;
        }

        // fold-exchange multi-reduce: 16 values x 32 lanes -> S[k] on lanes 2k,2k+1
        float t8[8];
#pragma unroll
        for (int j = 0; j < 8; ++j) {
            const float send = h4 ? s[j] : s[j + 8];
            const float recv = __shfl_xor_sync(FULLMASK, send, 16);
            t8[j] = (h4 ? s[j + 8] : s[j]) + recv;
        }
        float t4v[4];
#pragma unroll
        for (int j = 0; j < 4; ++j) {
            const float send = h3 ? t8[j] : t8[j + 4];
            const float recv = __shfl_xor_sync(FULLMASK, send, 8);
            t4v[j] = (h3 ? t8[j + 4] : t8[j]) + recv;
        }
        float t2v[2];
#pragma unroll
        for (int j = 0; j < 2; ++j) {
            const float send = h2 ? t4v[j] : t4v[j + 2];
            const float recv = __shfl_xor_sync(FULLMASK, send, 4);
            t2v[j] = (h2 ? t4v[j + 2] : t4v[j]) + recv;
        }
        {
            const float send = h1 ? t2v[0] : t2v[1];
            const float recv = __shfl_xor_sync(FULLMASK, send, 2);
            t2v[0] = (h1 ? t2v[1] : t2v[0]) + recv;
        }
        float sv = t2v[0] + __shfl_xor_sync(FULLMASK, t2v[0], 1);
        sv *= 0.0625f;   // 1/sqrt(256); lane l holds S[l>>1]

        // softmax over 16 distinct values (1 exp per lane)
        float mx = sv;
        mx = fmaxf(mx, __shfl_xor_sync(FULLMASK, mx, 2));
        mx = fmaxf(mx, __shfl_xor_sync(FULLMASK, mx, 4));
        mx = fmaxf(mx, __shfl_xor_sync(FULLMASK, mx, 8));
        mx = fmaxf(mx, __shfl_xor_sync(FULLMASK, mx, 16));
        const float ev = __expf(sv - mx);
        float ss = ev;
        ss += __shfl_xor_sync(FULLMASK, ss, 2);
        ss += __shfl_xor_sync(FULLMASK, ss, 4);
        ss += __shfl_xor_sync(FULLMASK, ss, 8);
        ss += __shfl_xor_sync(FULLMASK, ss, 16);
        const float awl = ev / ss;

        // V-weighted sum (fp32 packed fma)
        u64t o2[4] = {0ull, 0ull, 0ull, 0ull};
#pragma unroll
        for (int k = 0; k < Kn; ++k) {
            const float aw = __shfl_sync(FULLMASK, awl, 2 * k);
            const int j = __shfl_sync(FULLMASK, idx_l, k);
            u64t vv2[4];
            h8top4(*(const uint4*)(Vbase + (size_t)j * Cdim + lane * 8), vv2);
            const u64t aw2 = pack2(aw, aw);
#pragma unroll
            for (int t = 0; t < 4; ++t) o2[t] = fma2p(aw2, vv2[t], o2[t]);
        }
        float r[8];
#pragma unroll
        for (int t = 0; t < 4; ++t) {
            const u64t r2 = add2p(o2[t], q2[t]);
            unpack2(r2, r[2 * t], r[2 * t + 1]);
        }

        float part = 0.f;
#pragma unroll
        for (int t = 0; t < 8; ++t) part += r[t];
        const float mean = wsum(part) * (1.f / Cdim);
        float vpart = 0.f;
#pragma unroll
        for (int t = 0; t < 8; ++t) { const float d = r[t] - mean; vpart += d * d; }
        const float var  = wsum(vpart) * (1.f / Cdim);
        const float rstd = rsqrtf(var + 1e-5f);

        const float4 ga = ((const float4*)(ln_g + i * Cdim))[2 * lane];
        const float4 gb = ((const float4*)(ln_g + i * Cdim))[2 * lane + 1];
        const float4 ba = ((const float4*)(ln_b + i * Cdim))[2 * lane];
        const float4 bb = ((const float4*)(ln_b + i * Cdim))[2 * lane + 1];
        const float al = alph[i];
        acc[0] += al * ((r[0] - mean) * rstd * ga.x + ba.x);
        acc[1] += al * ((r[1] - mean) * rstd * ga.y + ba.y);
        acc[2] += al * ((r[2] - mean) * rstd * ga.z + ba.z);
        acc[3] += al * ((r[3] - mean) * rstd * ga.w + ba.w);
        acc[4] += al * ((r[4] - mean) * rstd * gb.x + bb.x);
        acc[5] += al * ((r[5] - mean) * rstd * gb.y + bb.y);
        acc[6] += al * ((r[6] - mean) * rstd * gb.z + bb.z);
        acc[7] += al * ((r[7] - mean) * rstd * gb.w + bb.w);
    }

    // final residual + LN (x3 loaded late to cut live registers in mainloop)
    float x[8];
    h8tof(*(const uint4*)(g_X3h + (size_t)w * Cdim + lane * 8), x);
    float r[8];
#pragma unroll
    for (int t = 0; t < 8; ++t) r[t] = acc[t] + x[t];
    float part = 0.f;
#pragma unroll
    for (int t = 0; t < 8; ++t) part += r[t];
    const float mean = wsum(part) * (1.f / Cdim);
    float vpart = 0.f;
#pragma unroll
    for (int t = 0; t < 8; ++t) { const float d = r[t] - mean; vpart += d * d; }
    const float var  = wsum(vpart) * (1.f / Cdim);
    const float rstd = rsqrtf(var + 1e-5f);

    const float4 ga = ((const float4*)fn_g)[2 * lane];
    const float4 gb = ((const float4*)fn_g)[2 * lane + 1];
    const float4 ba = ((const float4*)fn_b)[2 * lane];
    const float4 bb = ((const float4*)fn_b)[2 * lane + 1];

    float4 oa, ob;
    oa.x = (r[0] - mean) * rstd * ga.x + ba.x;
    oa.y = (r[1] - mean) * rstd * ga.y + ba.y;
    oa.z = (r[2] - mean) * rstd * ga.z + ba.z;
    oa.w = (r[3] - mean) * rstd * ga.w + ba.w;
    ob.x = (r[4] - mean) * rstd * gb.x + bb.x;
    ob.y = (r[5] - mean) * rstd * gb.y + bb.y;
    ob.z = (r[6] - mean) * rstd * gb.z + bb.z;
    ob.w = (r[7] - mean) * rstd * gb.w + bb.w;

    float4* orow = (float4*)(out + (size_t)w * Cdim);
    orow[2 * lane]     = oa;
    orow[2 * lane + 1] = ob;
}

// --------------------------------- launch ----------------------------------
extern "C" void kernel_launch(void* const* d_in, const int* in_sizes, int n_in,
                              void* d_out, int out_size) {
    const float* x0   = (const float*)d_in[0];
    const float* x1   = (const float*)d_in[1];
    const float* x2   = (const float*)d_in[2];
    const float* x3   = (const float*)d_in[3];
    const int*   knn  = (const int*)d_in[4];
    const float* Wq   = (const float*)d_in[5];
    const float* bq   = (const float*)d_in[6];
    const float* Wk   = (const float*)d_in[7];
    const float* bk   = (const float*)d_in[8];
    const float* Wv   = (const float*)d_in[9];
    const float* bv   = (const float*)d_in[10];
    const float* ln_g = (const float*)d_in[11];
    const float* ln_b = (const float*)d_in[12];
    const float* Wg1  = (const float*)d_in[13];
    const float* bg1  = (const float*)d_in[14];
    const float* Wg2  = (const float*)d_in[15];
    const float* bg2  = (const float*)d_in[16];
    const float* fn_g = (const float*)d_in[17];
    const float* fn_b = (const float*)d_in[18];
    float* out = (float*)d_out;

    __half *Qp, *Kp, *Vp, *Hp, *X3h;
    cudaGetSymbolAddress((void**)&Qp,  g_Q);
    cudaGetSymbolAddress((void**)&Kp,  g_K);
    cudaGetSymbolAddress((void**)&Vp,  g_V);
    cudaGetSymbolAddress((void**)&Hp,  g_H);
    cudaGetSymbolAddress((void**)&X3h, g_X3h);

    cudaFuncSetAttribute(gemm_fp16_kernel,
                         cudaFuncAttributeMaxDynamicSharedMemorySize, SM_TOT);

    GemmJobs jobs;
    const float* xs[3] = {x0, x1, x2};
    const size_t S = (size_t)Mrows * Cdim;
    for (int i = 0; i < 3; ++i) {
        jobs.j[i]     = { xs[i], Wq + (size_t)i * Cdim * Cdim, bq + i * Cdim, Qp + (size_t)i * S, Cdim, 0, 0 };
        jobs.j[3 + i] = { X3h,   Wk + (size_t)i * Cdim * Cdim, bk + i * Cdim, Kp + (size_t)i * S, Cdim, 0, 1 };
        jobs.j[6 + i] = { X3h,   Wv + (size_t)i * Cdim * Cdim, bv + i * Cdim, Vp + (size_t)i * S, Cdim, 0, 1 };
    }
    jobs.j[9] = { X3h, Wg1, bg1, Hp, Hdim, 1, 1 };

    // 1) convert x3 to fp16 (feeds 7 of 10 GEMM jobs + attn residual)
    cvt_x3_kernel<<<(Mrows * Cdim / 4 + 255) / 256, 256>>>(x3);
    // 2) all GEMM work, balanced persistent grid (1 wave at 1 CTA/SM)
    gemm_fp16_kernel<<<GRID_CTAS, 256, SM_TOT>>>(jobs);
    // 3) fused gate + attention + LNs
    const int warpsBlocks = (Mrows * 32 + 255) / 256;   // 5000
    attn_kernel<<<warpsBlocks, 256>>>(knn, Wg2, bg2, ln_g, ln_b, fn_g, fn_b, out);
}

// round 12
// speedup vs baseline: 1.3578x; 1.3578x over previous
#include <cuda_runtime.h>
#include <cuda_fp16.h>
#include <cstdint>
#include <cstddef>

#define FULLMASK 0xffffffffu

constexpr int Bx    = 2;
constexpr int Npt   = 20000;
constexpr int Cdim  = 256;
constexpr int Kn    = 16;
constexpr int Hdim  = 128;
constexpr int Mrows = Bx * Npt;   // 40000

// ---------------- scratch (device globals: allocation-free) ----------------
__device__ __half g_Q[(size_t)3 * Mrows * Cdim];
__device__ __half g_K[(size_t)3 * Mrows * Cdim];
__device__ __half g_V[(size_t)3 * Mrows * Cdim];
__device__ __half g_H[(size_t)Mrows * Hdim];
__device__ __half g_X3h[(size_t)Mrows * Cdim];

// ---------------- fp16 GEMM (B-resident persistent + ldmatrix) ------------
struct GemmJob {
    const void*  A;        // float* (a_half=0) or __half* (a_half=1)
    const float* W;
    const float* bias;
    void*        C;
    int          ncols;
    int          relu;
    int          a_half;
};
struct GemmJobs { GemmJob j[10]; };

constexpr int BM = 128;               // M tile
constexpr int BK = 32;                // k chunk
constexpr int KTILES = Cdim / BK;     // 8
constexpr int LDSA = 40;              // A smem stride (halfs): LDSM conflict-free
constexpr int LDSB = 264;             // B smem stride (halfs): LDSM conflict-free
constexpr int WORKERS = 31;
constexpr int MTILES = (Mrows + BM - 1) / BM;   // 313

// dynamic smem carve
constexpr int SMB_OFF = 0;
constexpr int SMB_BYTES = 128 * LDSB * 2;          // 67584
constexpr int SMA_OFF = SMB_BYTES;
constexpr int SMA_BYTES = 2 * BM * LDSA * 2;       // 20480 (2 buffers)
constexpr int SM_TOT = SMA_OFF + SMA_BYTES;        // 88064

__device__ __forceinline__ uint32_t smem_u32(const void* p) {
    uint32_t a;
    asm("{ .reg .u64 t; cvta.to.shared.u64 t, %1; cvt.u32.u64 %0, t; }" : "=r"(a) : "l"(p));
    return a;
}
__device__ __forceinline__ uint2 f4toh4(float4 v) {
    union { __half2 h; unsigned u; } a, b;
    a.h = __floats2half2_rn(v.x, v.y);
    b.h = __floats2half2_rn(v.z, v.w);
    return make_uint2(a.u, b.u);
}
__device__ __forceinline__ void ldsm4(unsigned r[4], uint32_t addr) {
    asm volatile("ldmatrix.sync.aligned.m8n8.x4.shared.b16 {%0,%1,%2,%3}, [%4];"
        : "=r"(r[0]), "=r"(r[1]), "=r"(r[2]), "=r"(r[3]) : "r"(addr));
}
__device__ __forceinline__ void mma16(float c[4], const unsigned a[4], const unsigned b[2]) {
    asm volatile(
        "mma.sync.aligned.m16n8k16.row.col.f32.f16.f16.f32 "
        "{%0,%1,%2,%3}, {%4,%5,%6,%7}, {%8,%9}, {%0,%1,%2,%3};\n"
        : "+f"(c[0]), "+f"(c[1]), "+f"(c[2]), "+f"(c[3])
        : "r"(a[0]), "r"(a[1]), "r"(a[2]), "r"(a[3]), "r"(b[0]), "r"(b[1]));
}

__global__ __launch_bounds__(256, 2) void gemm_fp16_kernel(GemmJobs jobs) {
    GemmJob jb = jobs.j[blockIdx.z];
    const int yoff = (int)blockIdx.y * 128;
    if (yoff >= jb.ncols) return;

    extern __shared__ char sm[];
    __half* Bres = (__half*)(sm + SMB_OFF);
    __half* Asm  = (__half*)(sm + SMA_OFF);   // [2][BM][LDSA]

    const int tid  = threadIdx.x;
    const int lane = tid & 31;
    const int warp = tid >> 5;       // 0..7
    const int g    = lane >> 2;      // 0..7
    const int t4   = lane & 3;       // 0..3
    const int m0w  = (warp & 1) * 64;
    const int n0w  = (warp >> 1) * 32;

    const int lr = tid >> 3;         // 0..31 (fp32 staging row)
    const int lc = (tid & 7) * 4;    // 0,4,..,28
    const int hr0 = tid >> 2;        // fp16 staging row (0..63)
    const int hc  = (tid & 3) * 8;   // half-offset 0,8,16,24

    const int rowA = lane & 15;
    const int kA8  = (lane >> 4) * 8;
    const int rowB = (lane & 7) + ((lane >> 4) << 3);
    const int kB8  = ((lane >> 3) & 1) << 3;

    const uint32_t sA = smem_u32(Asm);
    const uint32_t sB = smem_u32(Bres);

    // ---- load resident B half (128 cols of this job) as fp16, once ----
    for (int idx = tid; idx < 128 * 64; idx += 256) {
        const int r  = idx >> 6;
        const int c4 = (idx & 63) * 4;
        const float4 v = *(const float4*)(jb.W + (size_t)(yoff + r) * Cdim + c4);
        *(uint2*)&Bres[r * LDSB + c4] = f4toh4(v);
    }
    __syncthreads();

    const int ldc = jb.ncols;
    const int aHalf = jb.a_half;

    for (int mt = (int)blockIdx.x; mt < MTILES; mt += WORKERS) {
        const int rowBase = mt * BM;

        float acc[4][4][4];
#pragma unroll
        for (int mtile = 0; mtile < 4; ++mtile)
#pragma unroll
            for (int nt = 0; nt < 4; ++nt)
#pragma unroll
                for (int e = 0; e < 4; ++e) acc[mtile][nt][e] = 0.f;

        // ---- prologue: stage chunk 0 into buf 0 ----
        if (aHalf) {
            const __half* Ah = (const __half*)jb.A;
#pragma unroll
            for (int i = 0; i < 2; ++i) {
                const int r = hr0 + i * 64;
                const int ra = min(rowBase + r, Mrows - 1);
                *(uint4*)&Asm[(0 * BM + r) * LDSA + hc] =
                    *(const uint4*)(Ah + (size_t)ra * Cdim + hc);
            }
        } else {
            const float* Af = (const float*)jb.A;
#pragma unroll
            for (int i = 0; i < 4; ++i) {
                const int ra = min(rowBase + lr + i * 32, Mrows - 1);
                const float4 v = *(const float4*)(Af + (size_t)ra * Cdim + lc);
                *(uint2*)&Asm[(0 * BM + lr + i * 32) * LDSA + lc] = f4toh4(v);
            }
        }
        __syncthreads();

        for (int kt = 0; kt < KTILES; ++kt) {
            const int buf = kt & 1;
            float4 aRegF[4];
            uint4  aRegH[2];
            if (kt + 1 < KTILES) {
                const int ko = (kt + 1) * BK;
                if (aHalf) {
                    const __half* Ah = (const __half*)jb.A;
#pragma unroll
                    for (int i = 0; i < 2; ++i) {
                        const int r = hr0 + i * 64;
                        const int ra = min(rowBase + r, Mrows - 1);
                        aRegH[i] = *(const uint4*)(Ah + (size_t)ra * Cdim + ko + hc);
                    }
                } else {
                    const float* Af = (const float*)jb.A;
#pragma unroll
                    for (int i = 0; i < 4; ++i) {
                        const int ra = min(rowBase + lr + i * 32, Mrows - 1);
                        aRegF[i] = *(const float4*)(Af + (size_t)ra * Cdim + ko + lc);
                    }
                }
            }
#pragma unroll
            for (int ks = 0; ks < 2; ++ks) {
                const int kloc = ks * 16;
                const int kglb = kt * BK + kloc;
                unsigned afr[4][4];
#pragma unroll
                for (int mtile = 0; mtile < 4; ++mtile) {
                    const uint32_t addr = sA +
                        (uint32_t)(((buf * BM) + m0w + mtile * 16 + rowA) * LDSA + kloc + kA8) * 2;
                    ldsm4(afr[mtile], addr);
                }
                unsigned bfr[4][2];
#pragma unroll
                for (int ntp = 0; ntp < 2; ++ntp) {
                    unsigned q[4];
                    const uint32_t addr = sB +
                        (uint32_t)((n0w + ntp * 16 + rowB) * LDSB + kglb + kB8) * 2;
                    ldsm4(q, addr);
                    bfr[2 * ntp][0]     = q[0];
                    bfr[2 * ntp][1]     = q[1];
                    bfr[2 * ntp + 1][0] = q[2];
                    bfr[2 * ntp + 1][1] = q[3];
                }
#pragma unroll
                for (int mtile = 0; mtile < 4; ++mtile)
#pragma unroll
                    for (int nt = 0; nt < 4; ++nt)
                        mma16(acc[mtile][nt], afr[mtile], bfr[nt]);
            }
            if (kt + 1 < KTILES) {
                const int nb = buf ^ 1;
                if (aHalf) {
#pragma unroll
                    for (int i = 0; i < 2; ++i) {
                        const int r = hr0 + i * 64;
                        *(uint4*)&Asm[(nb * BM + r) * LDSA + hc] = aRegH[i];
                    }
                } else {
#pragma unroll
                    for (int i = 0; i < 4; ++i)
                        *(uint2*)&Asm[(nb * BM + lr + i * 32) * LDSA + lc] = f4toh4(aRegF[i]);
                }
                __syncthreads();
            }
        }

        // epilogue: bias (+relu), fp16 store, row-guarded
#pragma unroll
        for (int mtile = 0; mtile < 4; ++mtile) {
#pragma unroll
            for (int nt = 0; nt < 4; ++nt) {
                const int row = rowBase + m0w + mtile * 16 + g;
                const int col = yoff + n0w + nt * 8 + t4 * 2;
                const float b0 = jb.bias[col];
                const float b1 = jb.bias[col + 1];
                float v0 = acc[mtile][nt][0] + b0;
                float v1 = acc[mtile][nt][1] + b1;
                float v2 = acc[mtile][nt][2] + b0;
                float v3 = acc[mtile][nt][3] + b1;
                if (jb.relu) {
                    v0 = fmaxf(v0, 0.f); v1 = fmaxf(v1, 0.f);
                    v2 = fmaxf(v2, 0.f); v3 = fmaxf(v3, 0.f);
                }
                __half* C = (__half*)jb.C;
                if (row < Mrows)
                    *(__half2*)(C + (size_t)row * ldc + col) = __floats2half2_rn(v0, v1);
                if (row + 8 < Mrows)
                    *(__half2*)(C + (size_t)(row + 8) * ldc + col) = __floats2half2_rn(v2, v3);
            }
        }
        __syncthreads();   // A-buffer reads done before next tile's staging
    }
}

// ---------------- x3 -> fp16 convert --------------------------------------
__global__ __launch_bounds__(256) void cvt_x3_kernel(const float* __restrict__ x3) {
    const int idx = (int)(blockIdx.x * blockDim.x + threadIdx.x);   // 4 floats each
    const float4 v = ((const float4*)x3)[idx];
    *(uint2*)&g_X3h[(size_t)idx * 4] = f4toh4(v);
}

// ---------------- warp sum ------------------------------------------------
__device__ __forceinline__ float wsum(float p) {
#pragma unroll
    for (int off = 16; off; off >>= 1) p += __shfl_xor_sync(FULLMASK, p, off);
    return p;
}

// ------- fused: gate + KNN attention x3 + LN x3 + alpha + final LN --------
__device__ __forceinline__ void h8tof(uint4 v, float f[8]) {
    const __half2* h = (const __half2*)&v;
    const float2 a = __half22float2(h[0]);
    const float2 b = __half22float2(h[1]);
    const float2 c = __half22float2(h[2]);
    const float2 d = __half22float2(h[3]);
    f[0] = a.x; f[1] = a.y; f[2] = b.x; f[3] = b.y;
    f[4] = c.x; f[5] = c.y; f[6] = d.x; f[7] = d.y;
}

// ---- packed f32x2 helpers (sm_100+ PTX, no 'a' suffix required) ----
typedef unsigned long long u64t;
__device__ __forceinline__ u64t pack2(float lo, float hi) {
    u64t d;
    asm("mov.b64 %0, {%1, %2};" : "=l"(d) : "f"(lo), "f"(hi));
    return d;
}
__device__ __forceinline__ void unpack2(u64t d, float& lo, float& hi) {
    asm("mov.b64 {%0, %1}, %2;" : "=f"(lo), "=f"(hi) : "l"(d));
}
__device__ __forceinline__ u64t fma2p(u64t a, u64t b, u64t c) {
    u64t d;
    asm("fma.rn.f32x2 %0, %1, %2, %3;" : "=l"(d) : "l"(a), "l"(b), "l"(c));
    return d;
}
__device__ __forceinline__ u64t add2p(u64t a, u64t b) {
    u64t d;
    asm("add.rn.f32x2 %0, %1, %2;" : "=l"(d) : "l"(a), "l"(b));
    return d;
}
__device__ __forceinline__ void h8top4(uint4 v, u64t p[4]) {
    const __half2* h = (const __half2*)&v;
#pragma unroll
    for (int i = 0; i < 4; ++i) {
        const float2 f = __half22float2(h[i]);
        p[i] = pack2(f.x, f.y);
    }
}

__global__ __launch_bounds__(256, 3) void attn_kernel(
    const int* __restrict__ knn,
    const float* __restrict__ Wg2, const float* __restrict__ bg2,
    const float* __restrict__ ln_g, const float* __restrict__ ln_b,
    const float* __restrict__ fn_g, const float* __restrict__ fn_b,
    float* __restrict__ out) {
    const int w    = (int)((blockIdx.x * blockDim.x + threadIdx.x) >> 5);
    const int lane = threadIdx.x & 31;
    if (w >= Mrows) return;
    const int b = w / Npt;
    const int n = w - b * Npt;

    const int idx_l = (lane < Kn) ? knn[n * Kn + lane] : 0;

    // ---- inline gate: alpha = softmax(h @ Wg2^T + bg2) ----
    float alph[3];
    {
        const uint2 hv = *(const uint2*)(g_H + (size_t)w * Hdim + lane * 4);
        const __half2* hh = (const __half2*)&hv;
        const float2 h01 = __half22float2(hh[0]);
        const float2 h23 = __half22float2(hh[1]);
        float d[3];
#pragma unroll
        for (int i = 0; i < 3; ++i) {
            const float4 ww = ((const float4*)(Wg2 + i * Hdim))[lane];
            float p = h01.x * ww.x + h01.y * ww.y + h23.x * ww.z + h23.y * ww.w;
            d[i] = wsum(p) + bg2[i];
        }
        const float m  = fmaxf(d[0], fmaxf(d[1], d[2]));
        const float e0 = __expf(d[0] - m);
        const float e1 = __expf(d[1] - m);
        const float e2 = __expf(d[2] - m);
        const float inv = 1.f / (e0 + e1 + e2);
        alph[0] = e0 * inv; alph[1] = e1 * inv; alph[2] = e2 * inv;
    }

    const bool h4 = (lane & 16) != 0;
    const bool h3 = (lane & 8)  != 0;
    const bool h2 = (lane & 4)  != 0;
    const bool h1 = (lane & 2)  != 0;

    float acc[8] = {0.f, 0.f, 0.f, 0.f, 0.f, 0.f, 0.f, 0.f};

    for (int i = 0; i < 3; ++i) {
        const uint4 qraw = *(const uint4*)(g_Q + ((size_t)i * Mrows + w) * Cdim + lane * 8);
        const __half2* qh = (const __half2*)&qraw;
        u64t q2[4];
        h8top4(qraw, q2);
        const __half* Kbase = g_K + ((size_t)i * Mrows + (size_t)b * Npt) * Cdim;
        const __half* Vbase = g_V + ((size_t)i * Mrows + (size_t)b * Npt) * Cdim;

        // per-lane partial dots for all 16 neighbors (fp16 accumulate)
        float s[Kn];
#pragma unroll
        for (int k = 0; k < Kn; ++k) {
            const int j = __shfl_sync(FULLMASK, idx_l, k);
            const uint4 kvr = *(const uint4*)(Kbase + (size_t)j * Cdim + lane * 8);
            const __half2* kh = (const __half2*)&kvr;
            __half2 a0 = __hmul2(qh[0], kh[0]);
            __half2 a1 = __hmul2(qh[1], kh[1]);
            a0 = __hfma2(qh[2], kh[2], a0);
            a1 = __hfma2(qh[3], kh[3], a1);
            const float2 f = __half22float2(__hadd2(a0, a1));
            s[k] = f.x + f.y;
        }

        // fold-exchange multi-reduce: 16 values x 32 lanes -> S[k] on lanes 2k,2k+1
        float t8[8];
#pragma unroll
        for (int j = 0; j < 8; ++j) {
            const float send = h4 ? s[j] : s[j + 8];
            const float recv = __shfl_xor_sync(FULLMASK, send, 16);
            t8[j] = (h4 ? s[j + 8] : s[j]) + recv;
        }
        float t4v[4];
#pragma unroll
        for (int j = 0; j < 4; ++j) {
            const float send = h3 ? t8[j] : t8[j + 4];
            const float recv = __shfl_xor_sync(FULLMASK, send, 8);
            t4v[j] = (h3 ? t8[j + 4] : t8[j]) + recv;
        }
        float t2v[2];
#pragma unroll
        for (int j = 0; j < 2; ++j) {
            const float send = h2 ? t4v[j] : t4v[j + 2];
            const float recv = __shfl_xor_sync(FULLMASK, send, 4);
            t2v[j] = (h2 ? t4v[j + 2] : t4v[j]) + recv;
        }
        {
            const float send = h1 ? t2v[0] : t2v[1];
            const float recv = __shfl_xor_sync(FULLMASK, send, 2);
            t2v[0] = (h1 ? t2v[1] : t2v[0]) + recv;
        }
        float sv = t2v[0] + __shfl_xor_sync(FULLMASK, t2v[0], 1);
        sv *= 0.0625f;   // 1/sqrt(256); lane l holds S[l>>1]

        // softmax over 16 distinct values (1 exp per lane)
        float mx = sv;
        mx = fmaxf(mx, __shfl_xor_sync(FULLMASK, mx, 2));
        mx = fmaxf(mx, __shfl_xor_sync(FULLMASK, mx, 4));
        mx = fmaxf(mx, __shfl_xor_sync(FULLMASK, mx, 8));
        mx = fmaxf(mx, __shfl_xor_sync(FULLMASK, mx, 16));
        const float ev = __expf(sv - mx);
        float ss = ev;
        ss += __shfl_xor_sync(FULLMASK, ss, 2);
        ss += __shfl_xor_sync(FULLMASK, ss, 4);
        ss += __shfl_xor_sync(FULLMASK, ss, 8);
        ss += __shfl_xor_sync(FULLMASK, ss, 16);
        const float awl = ev / ss;

        // V-weighted sum (fp32 packed fma)
        u64t o2[4] = {0ull, 0ull, 0ull, 0ull};
#pragma unroll
        for (int k = 0; k < Kn; ++k) {
            const float aw = __shfl_sync(FULLMASK, awl, 2 * k);
            const int j = __shfl_sync(FULLMASK, idx_l, k);
            u64t vv2[4];
            h8top4(*(const uint4*)(Vbase + (size_t)j * Cdim + lane * 8), vv2);
            const u64t aw2 = pack2(aw, aw);
#pragma unroll
            for (int t = 0; t < 4; ++t) o2[t] = fma2p(aw2, vv2[t], o2[t]);
        }
        float r[8];
#pragma unroll
        for (int t = 0; t < 4; ++t) {
            const u64t r2 = add2p(o2[t], q2[t]);
            unpack2(r2, r[2 * t], r[2 * t + 1]);
        }

        float part = 0.f;
#pragma unroll
        for (int t = 0; t < 8; ++t) part += r[t];
        const float mean = wsum(part) * (1.f / Cdim);
        float vpart = 0.f;
#pragma unroll
        for (int t = 0; t < 8; ++t) { const float d = r[t] - mean; vpart += d * d; }
        const float var  = wsum(vpart) * (1.f / Cdim);
        const float rstd = rsqrtf(var + 1e-5f);

        const float4 ga = ((const float4*)(ln_g + i * Cdim))[2 * lane];
        const float4 gb = ((const float4*)(ln_g + i * Cdim))[2 * lane + 1];
        const float4 ba = ((const float4*)(ln_b + i * Cdim))[2 * lane];
        const float4 bb = ((const float4*)(ln_b + i * Cdim))[2 * lane + 1];
        const float al = alph[i];
        acc[0] += al * ((r[0] - mean) * rstd * ga.x + ba.x);
        acc[1] += al * ((r[1] - mean) * rstd * ga.y + ba.y);
        acc[2] += al * ((r[2] - mean) * rstd * ga.z + ba.z);
        acc[3] += al * ((r[3] - mean) * rstd * ga.w + ba.w);
        acc[4] += al * ((r[4] - mean) * rstd * gb.x + bb.x);
        acc[5] += al * ((r[5] - mean) * rstd * gb.y + bb.y);
        acc[6] += al * ((r[6] - mean) * rstd * gb.z + bb.z);
        acc[7] += al * ((r[7] - mean) * rstd * gb.w + bb.w);
    }

    // final residual + LN (x3 loaded late to cut live registers in mainloop)
    float x[8];
    h8tof(*(const uint4*)(g_X3h + (size_t)w * Cdim + lane * 8), x);
    float r[8];
#pragma unroll
    for (int t = 0; t < 8; ++t) r[t] = acc[t] + x[t];
    float part = 0.f;
#pragma unroll
    for (int t = 0; t < 8; ++t) part += r[t];
    const float mean = wsum(part) * (1.f / Cdim);
    float vpart = 0.f;
#pragma unroll
    for (int t = 0; t < 8; ++t) { const float d = r[t] - mean; vpart += d * d; }
    const float var  = wsum(vpart) * (1.f / Cdim);
    const float rstd = rsqrtf(var + 1e-5f);

    const float4 ga = ((const float4*)fn_g)[2 * lane];
    const float4 gb = ((const float4*)fn_g)[2 * lane + 1];
    const float4 ba = ((const float4*)fn_b)[2 * lane];
    const float4 bb = ((const float4*)fn_b)[2 * lane + 1];

    float4 oa, ob;
    oa.x = (r[0] - mean) * rstd * ga.x + ba.x;
    oa.y = (r[1] - mean) * rstd * ga.y + ba.y;
    oa.z = (r[2] - mean) * rstd * ga.z + ba.z;
    oa.w = (r[3] - mean) * rstd * ga.w + ba.w;
    ob.x = (r[4] - mean) * rstd * gb.x + bb.x;
    ob.y = (r[5] - mean) * rstd * gb.y + bb.y;
    ob.z = (r[6] - mean) * rstd * gb.z + bb.z;
    ob.w = (r[7] - mean) * rstd * gb.w + bb.w;

    float4* orow = (float4*)(out + (size_t)w * Cdim);
    orow[2 * lane]     = oa;
    orow[2 * lane + 1] = ob;
}

// --------------------------------- launch ----------------------------------
extern "C" void kernel_launch(void* const* d_in, const int* in_sizes, int n_in,
                              void* d_out, int out_size) {
    const float* x0   = (const float*)d_in[0];
    const float* x1   = (const float*)d_in[1];
    const float* x2   = (const float*)d_in[2];
    const float* x3   = (const float*)d_in[3];
    const int*   knn  = (const int*)d_in[4];
    const float* Wq   = (const float*)d_in[5];
    const float* bq   = (const float*)d_in[6];
    const float* Wk   = (const float*)d_in[7];
    const float* bk   = (const float*)d_in[8];
    const float* Wv   = (const float*)d_in[9];
    const float* bv   = (const float*)d_in[10];
    const float* ln_g = (const float*)d_in[11];
    const float* ln_b = (const float*)d_in[12];
    const float* Wg1  = (const float*)d_in[13];
    const float* bg1  = (const float*)d_in[14];
    const float* Wg2  = (const float*)d_in[15];
    const float* bg2  = (const float*)d_in[16];
    const float* fn_g = (const float*)d_in[17];
    const float* fn_b = (const float*)d_in[18];
    float* out = (float*)d_out;

    __half *Qp, *Kp, *Vp, *Hp, *X3h;
    cudaGetSymbolAddress((void**)&Qp,  g_Q);
    cudaGetSymbolAddress((void**)&Kp,  g_K);
    cudaGetSymbolAddress((void**)&Vp,  g_V);
    cudaGetSymbolAddress((void**)&Hp,  g_H);
    cudaGetSymbolAddress((void**)&X3h, g_X3h);

    cudaFuncSetAttribute(gemm_fp16_kernel,
                         cudaFuncAttributeMaxDynamicSharedMemorySize, SM_TOT);

    GemmJobs jobs;
    const float* xs[3] = {x0, x1, x2};
    const size_t S = (size_t)Mrows * Cdim;
    for (int i = 0; i < 3; ++i) {
        jobs.j[i]     = { xs[i], Wq + (size_t)i * Cdim * Cdim, bq + i * Cdim, Qp + (size_t)i * S, Cdim, 0, 0 };
        jobs.j[3 + i] = { X3h,   Wk + (size_t)i * Cdim * Cdim, bk + i * Cdim, Kp + (size_t)i * S, Cdim, 0, 1 };
        jobs.j[6 + i] = { X3h,   Wv + (size_t)i * Cdim * Cdim, bv + i * Cdim, Vp + (size_t)i * S, Cdim, 0, 1 };
    }
    jobs.j[9] = { X3h, Wg1, bg1, Hp, Hdim, 1, 1 };

    // 1) convert x3 to fp16 (feeds 7 of 10 GEMM jobs + attn residual)
    cvt_x3_kernel<<<(Mrows * Cdim / 4 + 255) / 256, 256>>>(x3);
    // 2) all 10 GEMM jobs in ONE launch (mixed A dtypes via per-job flag)
    dim3 gg(WORKERS, 2, 10);
    gemm_fp16_kernel<<<gg, 256, SM_TOT>>>(jobs);
    // 3) fused gate + attention + LNs
    const int warpsBlocks = (Mrows * 32 + 255) / 256;   // 5000
    attn_kernel<<<warpsBlocks, 256>>>(knn, Wg2, bg2, ln_g, ln_b, fn_g, fn_b, out);
}

// round 13
// speedup vs baseline: 1.4043x; 1.0342x over previous
#include <cuda_runtime.h>
#include <cuda_fp16.h>
#include <cstdint>
#include <cstddef>

#define FULLMASK 0xffffffffu

constexpr int Bx    = 2;
constexpr int Npt   = 20000;
constexpr int Cdim  = 256;
constexpr int Kn    = 16;
constexpr int Hdim  = 128;
constexpr int Mrows = Bx * Npt;   // 40000

// ---------------- scratch (device globals: allocation-free) ----------------
__device__ __half g_Q[(size_t)3 * Mrows * Cdim];
__device__ __half g_K[(size_t)3 * Mrows * Cdim];
__device__ __half g_V[(size_t)3 * Mrows * Cdim];
__device__ __half g_H[(size_t)Mrows * Hdim];
__device__ __half g_X3h[(size_t)Mrows * Cdim];

// ---------------- fp16 GEMM (B-resident persistent + ldmatrix) ------------
struct GemmJob {
    const void*  A;        // float* (a_half=0) or __half* (a_half=1)
    const float* W;
    const float* bias;
    void*        C;
    int          ncols;
    int          relu;
    int          a_half;
};
struct GemmJobs { GemmJob j[10]; };

constexpr int BM = 128;               // M tile
constexpr int BK = 32;                // k chunk
constexpr int KTILES = Cdim / BK;     // 8
constexpr int LDSA = 40;              // A smem stride (halfs): LDSM conflict-free
constexpr int LDSB = 264;             // B smem stride (halfs): LDSM conflict-free
constexpr int WORKERS = 31;
constexpr int MTILES = (Mrows + BM - 1) / BM;   // 313

// dynamic smem carve (3 A buffers for cp.async pipeline; fp32 path uses 0/1)
constexpr int SMB_OFF = 0;
constexpr int SMB_BYTES = 128 * LDSB * 2;          // 67584
constexpr int SMA_OFF = SMB_BYTES;
constexpr int SMA_BYTES = 3 * BM * LDSA * 2;       // 30720
constexpr int SM_TOT = SMA_OFF + SMA_BYTES;        // 98304

__device__ __forceinline__ uint32_t smem_u32(const void* p) {
    uint32_t a;
    asm("{ .reg .u64 t; cvta.to.shared.u64 t, %1; cvt.u32.u64 %0, t; }" : "=r"(a) : "l"(p));
    return a;
}
__device__ __forceinline__ uint2 f4toh4(float4 v) {
    union { __half2 h; unsigned u; } a, b;
    a.h = __floats2half2_rn(v.x, v.y);
    b.h = __floats2half2_rn(v.z, v.w);
    return make_uint2(a.u, b.u);
}
__device__ __forceinline__ void ldsm4(unsigned r[4], uint32_t addr) {
    asm volatile("ldmatrix.sync.aligned.m8n8.x4.shared.b16 {%0,%1,%2,%3}, [%4];"
        : "=r"(r[0]), "=r"(r[1]), "=r"(r[2]), "=r"(r[3]) : "r"(addr));
}
__device__ __forceinline__ void mma16(float c[4], const unsigned a[4], const unsigned b[2]) {
    asm volatile(
        "mma.sync.aligned.m16n8k16.row.col.f32.f16.f16.f32 "
        "{%0,%1,%2,%3}, {%4,%5,%6,%7}, {%8,%9}, {%0,%1,%2,%3};\n"
        : "+f"(c[0]), "+f"(c[1]), "+f"(c[2]), "+f"(c[3])
        : "r"(a[0]), "r"(a[1]), "r"(a[2]), "r"(a[3]), "r"(b[0]), "r"(b[1]));
}
#define CP16(dst, src) \
    asm volatile("cp.async.cg.shared.global [%0], [%1], 16;" :: "r"(dst), "l"(src))
#define CP_COMMIT() asm volatile("cp.async.commit_group;" ::: "memory")
#define CP_WAIT1()  asm volatile("cp.async.wait_group 1;" ::: "memory")
#define CP_WAIT0()  asm volatile("cp.async.wait_group 0;" ::: "memory")

__global__ __launch_bounds__(256, 2) void gemm_fp16_kernel(GemmJobs jobs) {
    GemmJob jb = jobs.j[blockIdx.z];
    const int yoff = (int)blockIdx.y * 128;
    if (yoff >= jb.ncols) return;

    extern __shared__ char sm[];
    __half* Bres = (__half*)(sm + SMB_OFF);
    __half* Asm  = (__half*)(sm + SMA_OFF);   // [3][BM][LDSA]

    const int tid  = threadIdx.x;
    const int lane = tid & 31;
    const int warp = tid >> 5;       // 0..7
    const int g    = lane >> 2;      // 0..7
    const int t4   = lane & 3;       // 0..3
    const int m0w  = (warp & 1) * 64;
    const int n0w  = (warp >> 1) * 32;

    const int lr = tid >> 3;         // 0..31 (fp32 staging row)
    const int lc = (tid & 7) * 4;    // 0,4,..,28
    const int hr0 = tid >> 2;        // fp16 staging row (0..63)
    const int hc  = (tid & 3) * 8;   // half-offset 0,8,16,24

    const int rowA = lane & 15;
    const int kA8  = (lane >> 4) * 8;
    const int rowB = (lane & 7) + ((lane >> 4) << 3);
    const int kB8  = ((lane >> 3) & 1) << 3;

    const uint32_t sA = smem_u32(Asm);
    const uint32_t sB = smem_u32(Bres);

    // ---- load resident B half (128 cols of this job) as fp16, once ----
    for (int idx = tid; idx < 128 * 64; idx += 256) {
        const int r  = idx >> 6;
        const int c4 = (idx & 63) * 4;
        const float4 v = *(const float4*)(jb.W + (size_t)(yoff + r) * Cdim + c4);
        *(uint2*)&Bres[r * LDSB + c4] = f4toh4(v);
    }
    __syncthreads();

    const int ldc = jb.ncols;
    const int aHalf = jb.a_half;

    for (int mt = (int)blockIdx.x; mt < MTILES; mt += WORKERS) {
        const int rowBase = mt * BM;

        float acc[4][4][4];
#pragma unroll
        for (int mtile = 0; mtile < 4; ++mtile)
#pragma unroll
            for (int nt = 0; nt < 4; ++nt)
#pragma unroll
                for (int e = 0; e < 4; ++e) acc[mtile][nt][e] = 0.f;

        if (aHalf) {
            // ---- cp.async 3-buffer pipeline, one barrier per chunk ----
            const __half* Ah = (const __half*)jb.A;
            auto stageH = [&](int kt, int b) {
#pragma unroll
                for (int i = 0; i < 2; ++i) {
                    const int r = hr0 + i * 64;
                    const int ra = min(rowBase + r, Mrows - 1);
                    const uint32_t dst = sA + (uint32_t)(((b * BM) + r) * LDSA + hc) * 2;
                    const __half* src = Ah + (size_t)ra * Cdim + kt * BK + hc;
                    CP16(dst, src);
                }
                CP_COMMIT();
            };
            stageH(0, 0);
            stageH(1, 1);

            for (int kt = 0; kt < KTILES; ++kt) {
                const int buf = kt % 3;
                if (kt < KTILES - 1) { CP_WAIT1(); } else { CP_WAIT0(); }
                __syncthreads();   // chunk kt visible; compute(kt-1) closed
                if (kt + 2 < KTILES) stageH(kt + 2, (kt + 2) % 3);
#pragma unroll
                for (int ks = 0; ks < 2; ++ks) {
                    const int kloc = ks * 16;
                    const int kglb = kt * BK + kloc;
                    unsigned afr[4][4];
#pragma unroll
                    for (int mtile = 0; mtile < 4; ++mtile) {
                        const uint32_t addr = sA +
                            (uint32_t)(((buf * BM) + m0w + mtile * 16 + rowA) * LDSA + kloc + kA8) * 2;
                        ldsm4(afr[mtile], addr);
                    }
                    unsigned bfr[4][2];
#pragma unroll
                    for (int ntp = 0; ntp < 2; ++ntp) {
                        unsigned q[4];
                        const uint32_t addr = sB +
                            (uint32_t)((n0w + ntp * 16 + rowB) * LDSB + kglb + kB8) * 2;
                        ldsm4(q, addr);
                        bfr[2 * ntp][0]     = q[0];
                        bfr[2 * ntp][1]     = q[1];
                        bfr[2 * ntp + 1][0] = q[2];
                        bfr[2 * ntp + 1][1] = q[3];
                    }
#pragma unroll
                    for (int mtile = 0; mtile < 4; ++mtile)
#pragma unroll
                        for (int nt = 0; nt < 4; ++nt)
                            mma16(acc[mtile][nt], afr[mtile], bfr[nt]);
                }
            }
        } else {
            // ---- fp32 A: register-staged double buffer (R12 path) ----
            const float* Af = (const float*)jb.A;
#pragma unroll
            for (int i = 0; i < 4; ++i) {
                const int ra = min(rowBase + lr + i * 32, Mrows - 1);
                const float4 v = *(const float4*)(Af + (size_t)ra * Cdim + lc);
                *(uint2*)&Asm[(0 * BM + lr + i * 32) * LDSA + lc] = f4toh4(v);
            }
            __syncthreads();

            for (int kt = 0; kt < KTILES; ++kt) {
                const int buf = kt & 1;
                float4 aRegF[4];
                if (kt + 1 < KTILES) {
                    const int ko = (kt + 1) * BK;
#pragma unroll
                    for (int i = 0; i < 4; ++i) {
                        const int ra = min(rowBase + lr + i * 32, Mrows - 1);
                        aRegF[i] = *(const float4*)(Af + (size_t)ra * Cdim + ko + lc);
                    }
                }
#pragma unroll
                for (int ks = 0; ks < 2; ++ks) {
                    const int kloc = ks * 16;
                    const int kglb = kt * BK + kloc;
                    unsigned afr[4][4];
#pragma unroll
                    for (int mtile = 0; mtile < 4; ++mtile) {
                        const uint32_t addr = sA +
                            (uint32_t)(((buf * BM) + m0w + mtile * 16 + rowA) * LDSA + kloc + kA8) * 2;
                        ldsm4(afr[mtile], addr);
                    }
                    unsigned bfr[4][2];
#pragma unroll
                    for (int ntp = 0; ntp < 2; ++ntp) {
                        unsigned q[4];
                        const uint32_t addr = sB +
                            (uint32_t)((n0w + ntp * 16 + rowB) * LDSB + kglb + kB8) * 2;
                        ldsm4(q, addr);
                        bfr[2 * ntp][0]     = q[0];
                        bfr[2 * ntp][1]     = q[1];
                        bfr[2 * ntp + 1][0] = q[2];
                        bfr[2 * ntp + 1][1] = q[3];
                    }
#pragma unroll
                    for (int mtile = 0; mtile < 4; ++mtile)
#pragma unroll
                        for (int nt = 0; nt < 4; ++nt)
                            mma16(acc[mtile][nt], afr[mtile], bfr[nt]);
                }
                if (kt + 1 < KTILES) {
                    const int nb = buf ^ 1;
#pragma unroll
                    for (int i = 0; i < 4; ++i)
                        *(uint2*)&Asm[(nb * BM + lr + i * 32) * LDSA + lc] = f4toh4(aRegF[i]);
                    __syncthreads();
                }
            }
        }

        // epilogue: bias (+relu), fp16 store, row-guarded
#pragma unroll
        for (int mtile = 0; mtile < 4; ++mtile) {
#pragma unroll
            for (int nt = 0; nt < 4; ++nt) {
                const int row = rowBase + m0w + mtile * 16 + g;
                const int col = yoff + n0w + nt * 8 + t4 * 2;
                const float b0 = jb.bias[col];
                const float b1 = jb.bias[col + 1];
                float v0 = acc[mtile][nt][0] + b0;
                float v1 = acc[mtile][nt][1] + b1;
                float v2 = acc[mtile][nt][2] + b0;
                float v3 = acc[mtile][nt][3] + b1;
                if (jb.relu) {
                    v0 = fmaxf(v0, 0.f); v1 = fmaxf(v1, 0.f);
                    v2 = fmaxf(v2, 0.f); v3 = fmaxf(v3, 0.f);
                }
                __half* C = (__half*)jb.C;
                if (row < Mrows)
                    *(__half2*)(C + (size_t)row * ldc + col) = __floats2half2_rn(v0, v1);
                if (row + 8 < Mrows)
                    *(__half2*)(C + (size_t)(row + 8) * ldc + col) = __floats2half2_rn(v2, v3);
            }
        }
        __syncthreads();   // A-buffer reads done before next tile's staging
    }
}

// ---------------- x3 -> fp16 convert --------------------------------------
__global__ __launch_bounds__(256) void cvt_x3_kernel(const float* __restrict__ x3) {
    const int idx = (int)(blockIdx.x * blockDim.x + threadIdx.x);   // 4 floats each
    const float4 v = ((const float4*)x3)[idx];
    *(uint2*)&g_X3h[(size_t)idx * 4] = f4toh4(v);
}

// ---------------- warp sum ------------------------------------------------
__device__ __forceinline__ float wsum(float p) {
#pragma unroll
    for (int off = 16; off; off >>= 1) p += __shfl_xor_sync(FULLMASK, p, off);
    return p;
}

// ------- fused: gate + KNN attention x3 + LN x3 + alpha + final LN --------
__device__ __forceinline__ void h8tof(uint4 v, float f[8]) {
    const __half2* h = (const __half2*)&v;
    const float2 a = __half22float2(h[0]);
    const float2 b = __half22float2(h[1]);
    const float2 c = __half22float2(h[2]);
    const float2 d = __half22float2(h[3]);
    f[0] = a.x; f[1] = a.y; f[2] = b.x; f[3] = b.y;
    f[4] = c.x; f[5] = c.y; f[6] = d.x; f[7] = d.y;
}

// ---- packed f32x2 helpers (sm_100+ PTX, no 'a' suffix required) ----
typedef unsigned long long u64t;
__device__ __forceinline__ u64t pack2(float lo, float hi) {
    u64t d;
    asm("mov.b64 %0, {%1, %2};" : "=l"(d) : "f"(lo), "f"(hi));
    return d;
}
__device__ __forceinline__ void unpack2(u64t d, float& lo, float& hi) {
    asm("mov.b64 {%0, %1}, %2;" : "=f"(lo), "=f"(hi) : "l"(d));
}
__device__ __forceinline__ u64t fma2p(u64t a, u64t b, u64t c) {
    u64t d;
    asm("fma.rn.f32x2 %0, %1, %2, %3;" : "=l"(d) : "l"(a), "l"(b), "l"(c));
    return d;
}
__device__ __forceinline__ u64t add2p(u64t a, u64t b) {
    u64t d;
    asm("add.rn.f32x2 %0, %1, %2;" : "=l"(d) : "l"(a), "l"(b));
    return d;
}
__device__ __forceinline__ void h8top4(uint4 v, u64t p[4]) {
    const __half2* h = (const __half2*)&v;
#pragma unroll
    for (int i = 0; i < 4; ++i) {
        const float2 f = __half22float2(h[i]);
        p[i] = pack2(f.x, f.y);
    }
}

__global__ __launch_bounds__(256, 3) void attn_kernel(
    const int* __restrict__ knn,
    const float* __restrict__ Wg2, const float* __restrict__ bg2,
    const float* __restrict__ ln_g, const float* __restrict__ ln_b,
    const float* __restrict__ fn_g, const float* __restrict__ fn_b,
    float* __restrict__ out) {
    const int w    = (int)((blockIdx.x * blockDim.x + threadIdx.x) >> 5);
    const int lane = threadIdx.x & 31;
    if (w >= Mrows) return;
    const int b = w / Npt;
    const int n = w - b * Npt;

    const int idx_l = (lane < Kn) ? knn[n * Kn + lane] : 0;

    // ---- inline gate: alpha = softmax(h @ Wg2^T + bg2) ----
    float alph[3];
    {
        const uint2 hv = *(const uint2*)(g_H + (size_t)w * Hdim + lane * 4);
        const __half2* hh = (const __half2*)&hv;
        const float2 h01 = __half22float2(hh[0]);
        const float2 h23 = __half22float2(hh[1]);
        float d[3];
#pragma unroll
        for (int i = 0; i < 3; ++i) {
            const float4 ww = ((const float4*)(Wg2 + i * Hdim))[lane];
            float p = h01.x * ww.x + h01.y * ww.y + h23.x * ww.z + h23.y * ww.w;
            d[i] = wsum(p) + bg2[i];
        }
        const float m  = fmaxf(d[0], fmaxf(d[1], d[2]));
        const float e0 = __expf(d[0] - m);
        const float e1 = __expf(d[1] - m);
        const float e2 = __expf(d[2] - m);
        const float inv = 1.f / (e0 + e1 + e2);
        alph[0] = e0 * inv; alph[1] = e1 * inv; alph[2] = e2 * inv;
    }

    const bool h4 = (lane & 16) != 0;
    const bool h3 = (lane & 8)  != 0;
    const bool h2 = (lane & 4)  != 0;
    const bool h1 = (lane & 2)  != 0;

    float acc[8] = {0.f, 0.f, 0.f, 0.f, 0.f, 0.f, 0.f, 0.f};

    for (int i = 0; i < 3; ++i) {
        const uint4 qraw = *(const uint4*)(g_Q + ((size_t)i * Mrows + w) * Cdim + lane * 8);
        const __half2* qh = (const __half2*)&qraw;
        u64t q2[4];
        h8top4(qraw, q2);
        const __half* Kbase = g_K + ((size_t)i * Mrows + (size_t)b * Npt) * Cdim;
        const __half* Vbase = g_V + ((size_t)i * Mrows + (size_t)b * Npt) * Cdim;

        // per-lane partial dots for all 16 neighbors (fp16 accumulate)
        float s[Kn];
#pragma unroll
        for (int k = 0; k < Kn; ++k) {
            const int j = __shfl_sync(FULLMASK, idx_l, k);
            const uint4 kvr = *(const uint4*)(Kbase + (size_t)j * Cdim + lane * 8);
            const __half2* kh = (const __half2*)&kvr;
            __half2 a0 = __hmul2(qh[0], kh[0]);
            __half2 a1 = __hmul2(qh[1], kh[1]);
            a0 = __hfma2(qh[2], kh[2], a0);
            a1 = __hfma2(qh[3], kh[3], a1);
            const float2 f = __half22float2(__hadd2(a0, a1));
            s[k] = f.x + f.y;
        }

        // fold-exchange multi-reduce: 16 values x 32 lanes -> S[k] on lanes 2k,2k+1
        float t8[8];
#pragma unroll
        for (int j = 0; j < 8; ++j) {
            const float send = h4 ? s[j] : s[j + 8];
            const float recv = __shfl_xor_sync(FULLMASK, send, 16);
            t8[j] = (h4 ? s[j + 8] : s[j]) + recv;
        }
        float t4v[4];
#pragma unroll
        for (int j = 0; j < 4; ++j) {
            const float send = h3 ? t8[j] : t8[j + 4];
            const float recv = __shfl_xor_sync(FULLMASK, send, 8);
            t4v[j] = (h3 ? t8[j + 4] : t8[j]) + recv;
        }
        float t2v[2];
#pragma unroll
        for (int j = 0; j < 2; ++j) {
            const float send = h2 ? t4v[j] : t4v[j + 2];
            const float recv = __shfl_xor_sync(FULLMASK, send, 4);
            t2v[j] = (h2 ? t4v[j + 2] : t4v[j]) + recv;
        }
        {
            const float send = h1 ? t2v[0] : t2v[1];
            const float recv = __shfl_xor_sync(FULLMASK, send, 2);
            t2v[0] = (h1 ? t2v[1] : t2v[0]) + recv;
        }
        float sv = t2v[0] + __shfl_xor_sync(FULLMASK, t2v[0], 1);
        sv *= 0.0625f;   // 1/sqrt(256); lane l holds S[l>>1]

        // softmax over 16 distinct values (1 exp per lane)
        float mx = sv;
        mx = fmaxf(mx, __shfl_xor_sync(FULLMASK, mx, 2));
        mx = fmaxf(mx, __shfl_xor_sync(FULLMASK, mx, 4));
        mx = fmaxf(mx, __shfl_xor_sync(FULLMASK, mx, 8));
        mx = fmaxf(mx, __shfl_xor_sync(FULLMASK, mx, 16));
        const float ev = __expf(sv - mx);
        float ss = ev;
        ss += __shfl_xor_sync(FULLMASK, ss, 2);
        ss += __shfl_xor_sync(FULLMASK, ss, 4);
        ss += __shfl_xor_sync(FULLMASK, ss, 8);
        ss += __shfl_xor_sync(FULLMASK, ss, 16);
        const float awl = ev / ss;

        // pack (fp16 aw[k], j[k]) into one word on lane k: single shfl in V loop
        const float awk = __shfl_sync(FULLMASK, awl, 2 * lane);  // lane k -> aw[k]
        const unsigned pk = ((unsigned)__half_as_ushort(__float2half_rn(awk)) << 16)
                          | ((unsigned)idx_l & 0xFFFFu);

        // V-weighted sum (fp32 packed fma)
        u64t o2[4] = {0ull, 0ull, 0ull, 0ull};
#pragma unroll
        for (int k = 0; k < Kn; ++k) {
            const unsigned p = __shfl_sync(FULLMASK, pk, k);
            const int j = (int)(p & 0xFFFFu);
            const float aw = __half2float(__ushort_as_half((unsigned short)(p >> 16)));
            u64t vv2[4];
            h8top4(*(const uint4*)(Vbase + (size_t)j * Cdim + lane * 8), vv2);
            const u64t aw2 = pack2(aw, aw);
#pragma unroll
            for (int t = 0; t < 4; ++t) o2[t] = fma2p(aw2, vv2[t], o2[t]);
        }
        float r[8];
#pragma unroll
        for (int t = 0; t < 4; ++t) {
            const u64t r2 = add2p(o2[t], q2[t]);
            unpack2(r2, r[2 * t], r[2 * t + 1]);
        }

        float part = 0.f;
#pragma unroll
        for (int t = 0; t < 8; ++t) part += r[t];
        const float mean = wsum(part) * (1.f / Cdim);
        float vpart = 0.f;
#pragma unroll
        for (int t = 0; t < 8; ++t) { const float d = r[t] - mean; vpart += d * d; }
        const float var  = wsum(vpart) * (1.f / Cdim);
        const float rstd = rsqrtf(var + 1e-5f);

        const float4 ga = ((const float4*)(ln_g + i * Cdim))[2 * lane];
        const float4 gb = ((const float4*)(ln_g + i * Cdim))[2 * lane + 1];
        const float4 ba = ((const float4*)(ln_b + i * Cdim))[2 * lane];
        const float4 bb = ((const float4*)(ln_b + i * Cdim))[2 * lane + 1];
        const float al = alph[i];
        acc[0] += al * ((r[0] - mean) * rstd * ga.x + ba.x);
        acc[1] += al * ((r[1] - mean) * rstd * ga.y + ba.y);
        acc[2] += al * ((r[2] - mean) * rstd * ga.z + ba.z);
        acc[3] += al * ((r[3] - mean) * rstd * ga.w + ba.w);
        acc[4] += al * ((r[4] - mean) * rstd * gb.x + bb.x);
        acc[5] += al * ((r[5] - mean) * rstd * gb.y + bb.y);
        acc[6] += al * ((r[6] - mean) * rstd * gb.z + bb.z);
        acc[7] += al * ((r[7] - mean) * rstd * gb.w + bb.w);
    }

    // final residual + LN (x3 loaded late to cut live registers in mainloop)
    float x[8];
    h8tof(*(const uint4*)(g_X3h + (size_t)w * Cdim + lane * 8), x);
    float r[8];
#pragma unroll
    for (int t = 0; t < 8; ++t) r[t] = acc[t] + x[t];
    float part = 0.f;
#pragma unroll
    for (int t = 0; t < 8; ++t) part += r[t];
    const float mean = wsum(part) * (1.f / Cdim);
    float vpart = 0.f;
#pragma unroll
    for (int t = 0; t < 8; ++t) { const float d = r[t] - mean; vpart += d * d; }
    const float var  = wsum(vpart) * (1.f / Cdim);
    const float rstd = rsqrtf(var + 1e-5f);

    const float4 ga = ((const float4*)fn_g)[2 * lane];
    const float4 gb = ((const float4*)fn_g)[2 * lane + 1];
    const float4 ba = ((const float4*)fn_b)[2 * lane];
    const float4 bb = ((const float4*)fn_b)[2 * lane + 1];

    float4 oa, ob;
    oa.x = (r[0] - mean) * rstd * ga.x + ba.x;
    oa.y = (r[1] - mean) * rstd * ga.y + ba.y;
    oa.z = (r[2] - mean) * rstd * ga.z + ba.z;
    oa.w = (r[3] - mean) * rstd * ga.w + ba.w;
    ob.x = (r[4] - mean) * rstd * gb.x + bb.x;
    ob.y = (r[5] - mean) * rstd * gb.y + bb.y;
    ob.z = (r[6] - mean) * rstd * gb.z + bb.z;
    ob.w = (r[7] - mean) * rstd * gb.w + bb.w;

    float4* orow = (float4*)(out + (size_t)w * Cdim);
    orow[2 * lane]     = oa;
    orow[2 * lane + 1] = ob;
}

// --------------------------------- launch ----------------------------------
extern "C" void kernel_launch(void* const* d_in, const int* in_sizes, int n_in,
                              void* d_out, int out_size) {
    const float* x0   = (const float*)d_in[0];
    const float* x1   = (const float*)d_in[1];
    const float* x2   = (const float*)d_in[2];
    const float* x3   = (const float*)d_in[3];
    const int*   knn  = (const int*)d_in[4];
    const float* Wq   = (const float*)d_in[5];
    const float* bq   = (const float*)d_in[6];
    const float* Wk   = (const float*)d_in[7];
    const float* bk   = (const float*)d_in[8];
    const float* Wv   = (const float*)d_in[9];
    const float* bv   = (const float*)d_in[10];
    const float* ln_g = (const float*)d_in[11];
    const float* ln_b = (const float*)d_in[12];
    const float* Wg1  = (const float*)d_in[13];
    const float* bg1  = (const float*)d_in[14];
    const float* Wg2  = (const float*)d_in[15];
    const float* bg2  = (const float*)d_in[16];
    const float* fn_g = (const float*)d_in[17];
    const float* fn_b = (const float*)d_in[18];
    float* out = (float*)d_out;

    __half *Qp, *Kp, *Vp, *Hp, *X3h;
    cudaGetSymbolAddress((void**)&Qp,  g_Q);
    cudaGetSymbolAddress((void**)&Kp,  g_K);
    cudaGetSymbolAddress((void**)&Vp,  g_V);
    cudaGetSymbolAddress((void**)&Hp,  g_H);
    cudaGetSymbolAddress((void**)&X3h, g_X3h);

    cudaFuncSetAttribute(gemm_fp16_kernel,
                         cudaFuncAttributeMaxDynamicSharedMemorySize, SM_TOT);

    GemmJobs jobs;
    const float* xs[3] = {x0, x1, x2};
    const size_t S = (size_t)Mrows * Cdim;
    for (int i = 0; i < 3; ++i) {
        jobs.j[i]     = { xs[i], Wq + (size_t)i * Cdim * Cdim, bq + i * Cdim, Qp + (size_t)i * S, Cdim, 0, 0 };
        jobs.j[3 + i] = { X3h,   Wk + (size_t)i * Cdim * Cdim, bk + i * Cdim, Kp + (size_t)i * S, Cdim, 0, 1 };
        jobs.j[6 + i] = { X3h,   Wv + (size_t)i * Cdim * Cdim, bv + i * Cdim, Vp + (size_t)i * S, Cdim, 0, 1 };
    }
    jobs.j[9] = { X3h, Wg1, bg1, Hp, Hdim, 1, 1 };

    // 1) convert x3 to fp16 (feeds 7 of 10 GEMM jobs + attn residual)
    cvt_x3_kernel<<<(Mrows * Cdim / 4 + 255) / 256, 256>>>(x3);
    // 2) all 10 GEMM jobs in ONE launch (mixed A dtypes via per-job flag)
    dim3 gg(WORKERS, 2, 10);
    gemm_fp16_kernel<<<gg, 256, SM_TOT>>>(jobs);
    // 3) fused gate + attention + LNs
    const int warpsBlocks = (Mrows * 32 + 255) / 256;   // 5000
    attn_kernel<<<warpsBlocks, 256>>>(knn, Wg2, bg2, ln_g, ln_b, fn_g, fn_b, out);
}